// round 2
// baseline (speedup 1.0000x reference)
#include <cuda_runtime.h>
#include <math.h>

#define D 32
#define H 128
#define B 128
#define NSTEPS 8
#define LOG2PI 1.8378770664093453f
#define DT 0.125f

// A[q][p] = W2[p][q] * M[q][p],  M = W1 @ W3  (so trace(J) = d2^T (A d1) with A row-indexed by q)
__device__ float g_A[H * H];

__global__ void prep_A_kernel(const float* __restrict__ W1,
                              const float* __restrict__ W2,
                              const float* __restrict__ W3) {
    int q = blockIdx.x;
    int p = threadIdx.x;
    float m = 0.f;
#pragma unroll
    for (int i = 0; i < D; ++i)
        m = fmaf(W1[q * D + i], W3[i * H + p], m);
    g_A[q * H + p] = W2[p * H + q] * m;
}

// Butcher tableau (DOPRI5)
__constant__ float c_c[6] = {0.f, 0.2f, 0.3f, 0.8f, 8.f / 9.f, 1.f};
__constant__ float c_a[6][5] = {
    {0.f, 0.f, 0.f, 0.f, 0.f},
    {0.2f, 0.f, 0.f, 0.f, 0.f},
    {3.f / 40.f, 9.f / 40.f, 0.f, 0.f, 0.f},
    {44.f / 45.f, -56.f / 15.f, 32.f / 9.f, 0.f, 0.f},
    {19372.f / 6561.f, -25360.f / 2187.f, 64448.f / 6561.f, -212.f / 729.f, 0.f},
    {9017.f / 3168.f, -355.f / 33.f, 46732.f / 5247.f, 49.f / 176.f, -5103.f / 18656.f}};
__constant__ float c_b[6] = {35.f / 384.f, 0.f, 500.f / 1113.f, 125.f / 192.f,
                             -2187.f / 6784.f, 11.f / 84.f};

// smem layout sizes (floats)
#define SZ_W1 (D * 129)      // W1c[k*129+p] = W1[p][k]
#define SZ_W2 (H * 129)      // W2c[q*129+p] = W2[p][q]
#define SZ_A  (H * 129)      // As [q*129+p] = A[q][p]
#define SZ_W3 (H * 33)       // W3c[p*33+i]  = W3[i][p]
// 8 arrays of 128 (u1s,b1s,b2s,h1s,d1s,h2s,trs,part), 4 arrays of 32
// (b3s,precs,xcur,xs), ks=6*34, red=4, scal=2 (+2 pad)
#define SMEM_FLOATS (SZ_W1 + SZ_W2 + SZ_A + SZ_W3 + 128 * 8 + 32 * 4 + 6 * 34 + 8)
#define SMEM_BYTES (SMEM_FLOATS * sizeof(float))

__global__ __launch_bounds__(H, 1) void ode_kernel(
    const float* __restrict__ x0g, const float* __restrict__ W1g,
    const float* __restrict__ u1g, const float* __restrict__ b1g,
    const float* __restrict__ W2g, const float* __restrict__ b2g,
    const float* __restrict__ W3g, const float* __restrict__ b3g,
    const float* __restrict__ precg, float* __restrict__ out) {
    extern __shared__ float sm[];
    float* W1c = sm;                  // [D][129]
    float* W2c = W1c + SZ_W1;         // [H][129]
    float* As  = W2c + SZ_W2;         // [H][129]
    float* W3c = As + SZ_A;           // [H][33]
    float* u1s = W3c + SZ_W3;         // 128
    float* b1s = u1s + H;             // 128
    float* b2s = b1s + H;             // 128
    float* h1s = b2s + H;             // 128
    float* d1s = h1s + H;             // 128
    float* h2s = d1s + H;             // 128
    float* trs = h2s + H;             // 128
    float* part = trs + H;            // 128
    float* b3s = part + H;            // 32
    float* precs = b3s + D;           // 32
    float* xcur = precs + D;          // 32
    float* xs = xcur + D;             // 32
    float* ks = xs + D;               // 6*34
    float* red = ks + 6 * 34;         // 4
    float* scal = red + 4;            // 2

    const int tid = threadIdx.x;
    const int b = blockIdx.x;

    // ---- stage weights into shared (coalesced global reads, conflict-free smem writes)
    for (int idx = tid; idx < H * D; idx += H) {        // W1: p=idx/32, k=idx%32
        int p = idx >> 5, k = idx & 31;
        W1c[k * 129 + p] = W1g[idx];
    }
    for (int idx = tid; idx < H * H; idx += H) {        // W2: p=idx/128, q=idx%128
        int p = idx >> 7, q = idx & 127;
        W2c[q * 129 + p] = W2g[idx];
    }
    for (int idx = tid; idx < H * H; idx += H) {        // A: q=idx/128, p=idx%128
        int q = idx >> 7, p = idx & 127;
        As[q * 129 + p] = g_A[idx];
    }
    for (int idx = tid; idx < D * H; idx += H) {        // W3: i=idx/128, p=idx%128
        int i = idx >> 7, p = idx & 127;
        W3c[p * 33 + i] = W3g[idx];
    }
    u1s[tid] = u1g[tid];
    b1s[tid] = b1g[tid];
    b2s[tid] = b2g[tid];
    if (tid < D) {
        b3s[tid] = b3g[tid];
        precs[tid] = precg[tid];
        xcur[tid] = x0g[b * D + tid];
    }
    if (tid == 0) { scal[0] = 0.f; scal[1] = 0.f; }
    __syncthreads();

    for (int s = 0; s < NSTEPS; ++s) {
        const float t0 = (float)s * DT;
        for (int st = 0; st < 6; ++st) {
            // stage input x
            if (tid < D) {
                float xv = xcur[tid];
                for (int j = 0; j < st; ++j)
                    xv = fmaf(DT * c_a[st][j], ks[j * 34 + tid], xv);
                xs[tid] = xv;
            }
            __syncthreads();
            const float t = fmaf(c_c[st], DT, t0);

            // h1 = tanh(W1 x + t u1 + b1)
            {
                float acc = 0.f;
#pragma unroll
                for (int k = 0; k < D; ++k)
                    acc = fmaf(W1c[k * 129 + tid], xs[k], acc);
                float z1 = fmaf(t, u1s[tid], acc + b1s[tid]);
                float h1 = tanhf(z1);
                h1s[tid] = h1;
                d1s[tid] = 1.f - h1 * h1;
            }
            __syncthreads();

            // z2 = W2 h1 ; av = A d1  (fused loop, 2 chains each)
            {
                float z2a = 0.f, z2b = 0.f, ava = 0.f, avb = 0.f;
#pragma unroll 8
                for (int q = 0; q < H; q += 2) {
                    z2a = fmaf(W2c[q * 129 + tid], h1s[q], z2a);
                    ava = fmaf(As[q * 129 + tid], d1s[q], ava);
                    z2b = fmaf(W2c[(q + 1) * 129 + tid], h1s[q + 1], z2b);
                    avb = fmaf(As[(q + 1) * 129 + tid], d1s[q + 1], avb);
                }
                float h2 = tanhf(z2a + z2b + b2s[tid]);
                h2s[tid] = h2;
                trs[tid] = (1.f - h2 * h2) * (ava + avb);
            }
            __syncthreads();

            // W3 partials: thread (i = tid&31, g = tid>>5)
            {
                const int i = tid & 31, g = tid >> 5;
                float o = 0.f;
#pragma unroll
                for (int pp = 0; pp < 32; ++pp) {
                    int prow = g * 32 + pp;
                    o = fmaf(W3c[prow * 33 + i], h2s[prow], o);
                }
                part[tid] = o;
            }
            // trace reduction (warp 1)
            if ((tid >> 5) == 1) {
                int l = tid & 31;
                float tsum = trs[l] + trs[l + 32] + trs[l + 64] + trs[l + 96];
#pragma unroll
                for (int off = 16; off; off >>= 1)
                    tsum += __shfl_down_sync(0xffffffffu, tsum, off);
                if (l == 0) red[2] = tsum;
            }
            __syncthreads();

            // finalize k_st (warp 0)
            if (tid < D) {
                float dx = part[tid] + part[tid + 32] + part[tid + 64] + part[tid + 96] + b3s[tid];
                ks[st * 34 + tid] = dx;
                float xv = xs[tid];
                float lp = fmaf(-0.5f * xv, xv, -0.5f * LOG2PI);
                float s1 = lp * dx;
                float s2 = -precs[tid] * xv * dx;
#pragma unroll
                for (int off = 16; off; off >>= 1) {
                    s1 += __shfl_down_sync(0xffffffffu, s1, off);
                    s2 += __shfl_down_sync(0xffffffffu, s2, off);
                }
                if (tid == 0) {
                    float trace = red[2];
                    float dlogp = -trace;
                    float omt = 1.f - t;
                    float dkl = fmaf(-0.5f * omt * omt, s1,
                                fmaf(-0.5f * omt * (1.f + t), s2, omt * dlogp));
                    ks[st * 34 + 32] = dlogp;
                    ks[st * 34 + 33] = dkl;
                }
            }
            __syncthreads();
        }
        // y update
        if (tid < D) {
            float xv = xcur[tid];
#pragma unroll
            for (int j = 0; j < 6; ++j)
                xv = fmaf(DT * c_b[j], ks[j * 34 + tid], xv);
            xcur[tid] = xv;
        } else if (tid == 32) {
            float a = scal[0];
#pragma unroll
            for (int j = 0; j < 6; ++j)
                a = fmaf(DT * c_b[j], ks[j * 34 + 32], a);
            scal[0] = a;
        } else if (tid == 33) {
            float a = scal[1];
#pragma unroll
            for (int j = 0; j < 6; ++j)
                a = fmaf(DT * c_b[j], ks[j * 34 + 33], a);
            scal[1] = a;
        }
        __syncthreads();
    }

    // outputs: z [B*D], then logp [B], then kl [B]
    if (tid < D) {
        out[b * D + tid] = xcur[tid];
        float x0v = x0g[b * D + tid];
        float lp = fmaf(-0.5f * x0v, x0v, -0.5f * LOG2PI);
#pragma unroll
        for (int off = 16; off; off >>= 1)
            lp += __shfl_down_sync(0xffffffffu, lp, off);
        if (tid == 0) {
            out[B * D + b] = lp + scal[0];
            out[B * D + B + b] = scal[1];
        }
    }
}

extern "C" void kernel_launch(void* const* d_in, const int* in_sizes, int n_in,
                              void* d_out, int out_size) {
    const float* x0 = (const float*)d_in[0];
    const float* W1 = (const float*)d_in[1];
    const float* u1 = (const float*)d_in[2];
    const float* b1 = (const float*)d_in[3];
    const float* W2 = (const float*)d_in[4];
    const float* b2 = (const float*)d_in[5];
    const float* W3 = (const float*)d_in[6];
    const float* b3 = (const float*)d_in[7];
    const float* prec = (const float*)d_in[8];
    float* out = (float*)d_out;

    prep_A_kernel<<<H, H>>>(W1, W2, W3);

    cudaFuncSetAttribute(ode_kernel, cudaFuncAttributeMaxDynamicSharedMemorySize,
                         (int)SMEM_BYTES);

    ode_kernel<<<B, H, SMEM_BYTES>>>(x0, W1, u1, b1, W2, b2, W3, b3, prec, out);
}

// round 3
// speedup vs baseline: 1.3767x; 1.3767x over previous
#include <cuda_runtime.h>
#include <math.h>

#define D 32
#define H 128
#define B 128
#define NSTEPS 8
#define NTHREADS 512
#define LOG2PI 1.8378770664093453f
#define DT 0.125f

// A[q][p] = W2[p][q] * M[q][p],  M = W1 @ W3  (trace(J) = d2^T (A d1))
__device__ float g_A[H * H];

__global__ void prep_A_kernel(const float* __restrict__ W1,
                              const float* __restrict__ W2,
                              const float* __restrict__ W3) {
    int q = blockIdx.x;
    int p = threadIdx.x;
    float m = 0.f;
#pragma unroll
    for (int i = 0; i < D; ++i)
        m = fmaf(W1[q * D + i], W3[i * H + p], m);
    g_A[q * H + p] = W2[p * H + q] * m;
}

__constant__ float c_c[6] = {0.f, 0.2f, 0.3f, 0.8f, 8.f / 9.f, 1.f};
__constant__ float c_a[6][5] = {
    {0.f, 0.f, 0.f, 0.f, 0.f},
    {0.2f, 0.f, 0.f, 0.f, 0.f},
    {3.f / 40.f, 9.f / 40.f, 0.f, 0.f, 0.f},
    {44.f / 45.f, -56.f / 15.f, 32.f / 9.f, 0.f, 0.f},
    {19372.f / 6561.f, -25360.f / 2187.f, 64448.f / 6561.f, -212.f / 729.f, 0.f},
    {9017.f / 3168.f, -355.f / 33.f, 46732.f / 5247.f, 49.f / 176.f, -5103.f / 18656.f}};
__constant__ float c_b[6] = {35.f / 384.f, 0.f, 500.f / 1113.f, 125.f / 192.f,
                             -2187.f / 6784.f, 11.f / 84.f};

// shared memory layout (floats)
// z1part[512], part2 (float2 x 512 = 1024), part[512], hd2 (float2 x 128 = 256),
// trs[128], h2s[128], u1s[128], b1s[128], b2s[128],
// xs[32], xcur[32], b3s[32], precs[32], ks[6*34], red[4], scal[4]
#define OFF_Z1PART 0
#define OFF_PART2  (OFF_Z1PART + 512)
#define OFF_PART   (OFF_PART2 + 1024)
#define OFF_HD2    (OFF_PART + 512)
#define OFF_TRS    (OFF_HD2 + 256)
#define OFF_H2S    (OFF_TRS + 128)
#define OFF_U1S    (OFF_H2S + 128)
#define OFF_B1S    (OFF_U1S + 128)
#define OFF_B2S    (OFF_B1S + 128)
#define OFF_XS     (OFF_B2S + 128)
#define OFF_XCUR   (OFF_XS + 32)
#define OFF_B3S    (OFF_XCUR + 32)
#define OFF_PRECS  (OFF_B3S + 32)
#define OFF_KS     (OFF_PRECS + 32)
#define OFF_RED    (OFF_KS + 6 * 34)
#define OFF_SCAL   (OFF_RED + 4)
#define SMEM_FLOATS (OFF_SCAL + 4)
#define SMEM_BYTES (SMEM_FLOATS * sizeof(float))

__global__ __launch_bounds__(NTHREADS, 1) void ode_kernel(
    const float* __restrict__ x0g, const float* __restrict__ W1g,
    const float* __restrict__ u1g, const float* __restrict__ b1g,
    const float* __restrict__ W2g, const float* __restrict__ b2g,
    const float* __restrict__ W3g, const float* __restrict__ b3g,
    const float* __restrict__ precg, float* __restrict__ out) {
    extern __shared__ float sm[];
    float* z1part = sm + OFF_Z1PART;
    float2* part2 = (float2*)(sm + OFF_PART2);
    float* part = sm + OFF_PART;
    float2* hd2 = (float2*)(sm + OFF_HD2);
    float* trs = sm + OFF_TRS;
    float* h2s = sm + OFF_H2S;
    float* u1s = sm + OFF_U1S;
    float* b1s = sm + OFF_B1S;
    float* b2s = sm + OFF_B2S;
    float* xs = sm + OFF_XS;
    float* xcur = sm + OFF_XCUR;
    float* b3s = sm + OFF_B3S;
    float* precs = sm + OFF_PRECS;
    float* ks = sm + OFF_KS;
    float* red = sm + OFF_RED;
    float* scal = sm + OFF_SCAL;

    const int tid = threadIdx.x;
    const int b = blockIdx.x;
    const int p = tid & 127;     // output index within H
    const int c = tid >> 7;      // chunk 0..3 over the q/k reduction dim
    const int i3 = tid & 31;     // W3 output index
    const int g3 = tid >> 5;     // W3 chunk 0..15

    // ---- register-cached weights (loaded once) ----
    float W2r[32], Ar[32], W1r[8], W3r[8];
#pragma unroll
    for (int j = 0; j < 32; ++j) {
        int q = c * 32 + j;
        W2r[j] = W2g[q * H + p];   // W2[p][q] needed: careful — see note below
        Ar[j] = g_A[q * H + p];
    }
    // NOTE: z2[p] = sum_q W2[p][q] h1[q]; W2g is row-major [p][q], so element = W2g[p*H+q].
    // Fix up: reload correctly (the loop above loaded W2[q][p] which is wrong for W2).
#pragma unroll
    for (int j = 0; j < 32; ++j) {
        int q = c * 32 + j;
        W2r[j] = W2g[p * H + q];
    }
#pragma unroll
    for (int j = 0; j < 8; ++j) {
        int k = c * 8 + j;
        W1r[j] = W1g[p * D + k];   // W1[p][k]
    }
#pragma unroll
    for (int j = 0; j < 8; ++j) {
        int pr = g3 * 8 + j;
        W3r[j] = W3g[i3 * H + pr]; // W3[i][p]
    }

    // ---- small params into shared ----
    if (tid < H) {
        u1s[tid] = u1g[tid];
        b1s[tid] = b1g[tid];
        b2s[tid] = b2g[tid];
    }
    if (tid < D) {
        b3s[tid] = b3g[tid];
        precs[tid] = precg[tid];
        xcur[tid] = x0g[b * D + tid];
    }
    if (tid == 0) { scal[0] = 0.f; scal[1] = 0.f; }
    __syncthreads();

    for (int s = 0; s < NSTEPS; ++s) {
        const float t0 = (float)s * DT;
        for (int st = 0; st < 6; ++st) {
            // ---- stage input x ----
            if (tid < D) {
                float xv = xcur[tid];
                for (int j = 0; j < st; ++j)
                    xv = fmaf(DT * c_a[st][j], ks[j * 34 + tid], xv);
                xs[tid] = xv;
            }
            __syncthreads();
            const float t = fmaf(c_c[st], DT, t0);

            // ---- z1 partials: thread (c,p), k-range 8 ----
            {
                float acc = 0.f;
#pragma unroll
                for (int j = 0; j < 8; ++j)
                    acc = fmaf(W1r[j], xs[c * 8 + j], acc);
                z1part[c * 128 + p] = acc;
            }
            __syncthreads();

            // ---- h1 finalize (first 128 threads) ----
            if (tid < H) {
                float z1 = z1part[tid] + z1part[128 + tid] + z1part[256 + tid] +
                           z1part[384 + tid];
                z1 = fmaf(t, u1s[tid], z1 + b1s[tid]);
                float h1 = tanhf(z1);
                hd2[tid] = make_float2(h1, 1.f - h1 * h1);
            }
            __syncthreads();

            // ---- hot loop: z2/av partials over q-chunk of 32 ----
            {
                float z2a = 0.f, z2b = 0.f, ava = 0.f, avb = 0.f;
                const int qb = c * 32;
#pragma unroll
                for (int j = 0; j < 32; j += 2) {
                    float2 hA = hd2[qb + j];
                    float2 hB = hd2[qb + j + 1];
                    z2a = fmaf(W2r[j], hA.x, z2a);
                    ava = fmaf(Ar[j], hA.y, ava);
                    z2b = fmaf(W2r[j + 1], hB.x, z2b);
                    avb = fmaf(Ar[j + 1], hB.y, avb);
                }
                part2[c * 128 + p] = make_float2(z2a + z2b, ava + avb);
            }
            __syncthreads();

            // ---- h2 finalize (first 128 threads) ----
            if (tid < H) {
                float2 a0 = part2[tid];
                float2 a1 = part2[128 + tid];
                float2 a2 = part2[256 + tid];
                float2 a3 = part2[384 + tid];
                float z2 = a0.x + a1.x + a2.x + a3.x + b2s[tid];
                float av = a0.y + a1.y + a2.y + a3.y;
                float h2 = tanhf(z2);
                h2s[tid] = h2;
                trs[tid] = (1.f - h2 * h2) * av;
            }
            __syncthreads();

            // ---- W3 partials (all threads), trace reduce (warp 1) ----
            {
                float o = 0.f;
#pragma unroll
                for (int j = 0; j < 8; ++j)
                    o = fmaf(W3r[j], h2s[g3 * 8 + j], o);
                part[g3 * 32 + i3] = o;
            }
            if ((tid >> 5) == 1) {
                int l = tid & 31;
                float tsum = trs[l] + trs[l + 32] + trs[l + 64] + trs[l + 96];
#pragma unroll
                for (int off = 16; off; off >>= 1)
                    tsum += __shfl_down_sync(0xffffffffu, tsum, off);
                if (l == 0) red[2] = tsum;
            }
            __syncthreads();

            // ---- finalize k_st (warp 0) ----
            if (tid < D) {
                float dx = b3s[tid];
#pragma unroll
                for (int g = 0; g < 16; ++g)
                    dx += part[g * 32 + tid];
                ks[st * 34 + tid] = dx;
                float xv = xs[tid];
                float lp = fmaf(-0.5f * xv, xv, -0.5f * LOG2PI);
                float s1 = lp * dx;
                float s2 = -precs[tid] * xv * dx;
#pragma unroll
                for (int off = 16; off; off >>= 1) {
                    s1 += __shfl_down_sync(0xffffffffu, s1, off);
                    s2 += __shfl_down_sync(0xffffffffu, s2, off);
                }
                if (tid == 0) {
                    float trace = red[2];
                    float dlogp = -trace;
                    float omt = 1.f - t;
                    float dkl = fmaf(-0.5f * omt * omt, s1,
                                fmaf(-0.5f * omt * (1.f + t), s2, omt * dlogp));
                    ks[st * 34 + 32] = dlogp;
                    ks[st * 34 + 33] = dkl;
                }
            }
            __syncthreads();

            (void)st;
        }
        // ---- y update ----
        if (tid < D) {
            float xv = xcur[tid];
#pragma unroll
            for (int j = 0; j < 6; ++j)
                xv = fmaf(DT * c_b[j], ks[j * 34 + tid], xv);
            xcur[tid] = xv;
        } else if (tid == 32) {
            float a = scal[0];
#pragma unroll
            for (int j = 0; j < 6; ++j)
                a = fmaf(DT * c_b[j], ks[j * 34 + 32], a);
            scal[0] = a;
        } else if (tid == 33) {
            float a = scal[1];
#pragma unroll
            for (int j = 0; j < 6; ++j)
                a = fmaf(DT * c_b[j], ks[j * 34 + 33], a);
            scal[1] = a;
        }
        __syncthreads();
    }

    // ---- outputs: z [B*D], logp [B], kl [B] ----
    if (tid < D) {
        out[b * D + tid] = xcur[tid];
        float x0v = x0g[b * D + tid];
        float lp = fmaf(-0.5f * x0v, x0v, -0.5f * LOG2PI);
#pragma unroll
        for (int off = 16; off; off >>= 1)
            lp += __shfl_down_sync(0xffffffffu, lp, off);
        if (tid == 0) {
            out[B * D + b] = lp + scal[0];
            out[B * D + B + b] = scal[1];
        }
    }
}

extern "C" void kernel_launch(void* const* d_in, const int* in_sizes, int n_in,
                              void* d_out, int out_size) {
    const float* x0 = (const float*)d_in[0];
    const float* W1 = (const float*)d_in[1];
    const float* u1 = (const float*)d_in[2];
    const float* b1 = (const float*)d_in[3];
    const float* W2 = (const float*)d_in[4];
    const float* b2 = (const float*)d_in[5];
    const float* W3 = (const float*)d_in[6];
    const float* b3 = (const float*)d_in[7];
    const float* prec = (const float*)d_in[8];
    float* out = (float*)d_out;

    prep_A_kernel<<<H, H>>>(W1, W2, W3);
    ode_kernel<<<B, NTHREADS, SMEM_BYTES>>>(x0, W1, u1, b1, W2, b2, W3, b3, prec, out);
}